// round 9
// baseline (speedup 1.0000x reference)
#include <cuda_runtime.h>
#include <math.h>

// ---------------- constants matching the reference ----------------
#define HH 121
#define WW 121
#define NE 225
#define NB 8
#define NSPLIT 4
#define N_INTERP 200
#define RET_PER_DVA 280.0f
#define XRANGE0 (-15.0f)
#define YRANGE0 (-15.0f)
#define XYSTEP 0.25f
#define XLOWc (-4200.0f)
#define YLOWc (-4200.0f)
#define STEP_Xc (8400.0f/199.0f)
#define STEP_Yc (8400.0f/199.0f)
#define OD_OFF_Xc (15.5f*280.0f)
#define AMP_CUTOFF 0.25f
#define PIc 3.14159265358979323846f
#define TEMP1c (4.0f*PIc)
#define NEG_HALF_LOG2E (-0.7213475204444817f)   // -0.5*log2(e)
#define LOG2_045 (-1.1520030934450498f)         // log2(0.45)

#define NPIX (HH*WW)
#define TILES_X 4
#define TILES_Y 8
#define EPB 29                         // electrodes per precompute block (ceil(225/8))

// compacted per-b table:  slot*2+0: (cx, cy2, -, bright)   slot*2+1: (c00, c01, c11, 2*c11)
__device__ float4 g_tab[NB][NE * 2];
__device__ int    g_cnt[NB];           // via atomicAdd, reset by main kernel finishers? no: recomputed
// partial images per electrode-split
__device__ float  g_part[NSPLIT * NB * NPIX];
// per-(b, tile) completion counters (statically zero; reset by finisher)
__device__ int    g_done[NB * TILES_X * TILES_Y];

__device__ __forceinline__ float ex2_fast(float x) {
    float r;
    asm("ex2.approx.ftz.f32 %0, %1;" : "=f"(r) : "f"(x));
    return r;
}

// ---------------- kernel A: per-electrode precompute ----------------
// grid (8 chunks, NB) x 32 threads; each warp handles 29 electrodes of one b.
// Compaction must be deterministic and globally ordered by e: we compute a
// per-warp offset from a per-(b,chunk) activity-count table written first...
// Simpler: skip compaction. Store ALL electrodes; inactive ones get
// bright=0 & coeffs=0 (t=0 -> ex2=0*? ) ... ex2(0)=1, bright=0 -> contributes 0.
// Main loop cost per electrode is identical whether culled or not was ~12.5%;
// trading that for zero cross-block coordination.
__global__ __launch_bounds__(32) void precompute_kernel(
        const float* __restrict__ stim,
        const float* __restrict__ params,
        const float* __restrict__ elec_x,
        const float* __restrict__ elec_y,
        const float* __restrict__ slopes) {
    int b = blockIdx.y;
    int e = blockIdx.x * EPB + threadIdx.x;   // gridDim.x = 8, 29*8=232 >= 225
    if (threadIdx.x >= EPB || e >= NE) return;

    const float* P = params + b * 13;
    float rho = P[0], lam = P[1], osc = P[2];
    float a0 = P[3], a1 = P[4], a2 = P[5], a3 = P[6], a4 = P[7];
    float impx = P[8], impy = P[9], rot = P[10], lodx = P[11];
    float cr = __cosf(rot), sr = __sinf(rot);

    float exv = elec_x[e] * cr - elec_y[e] * sr + impx;
    float eyv = elec_x[e] * sr + elec_y[e] * cr + impy;
    float freq = stim[(b * NE + e) * 3 + 0];
    float amp  = stim[(b * NE + e) * 3 + 1];
    float pdur = stim[(b * NE + e) * 3 + 2];

    float cx = 0.f, cy2 = 0.f, bright = 0.f;
    float c00 = 0.f, c01 = 0.f, c11 = 0.f;

    if (amp > AMP_CUTOFF) {
        float offx = lodx - OD_OFF_Xc;
        float qx = (exv - offx - XLOWc) * (1.0f / STEP_Xc);
        float qy = (eyv - YLOWc) * (1.0f / STEP_Yc);

        float fx = fminf(fmaxf(floorf(qx), 0.f), (float)(N_INTERP - 2));
        float fy = fminf(fmaxf(floorf(qy), 0.f), (float)(N_INTERP - 2));
        int ix = (int)fx, iy = (int)fy;
        float ax = fminf(fmaxf(qx - fx, 0.f), 1.f);
        float ay = fminf(fmaxf(qy - fy, 0.f), 1.f);
        float g00 = slopes[iy * N_INTERP + ix];
        float g01 = slopes[iy * N_INTERP + ix + 1];
        float g10 = slopes[(iy + 1) * N_INTERP + ix];
        float g11 = slopes[(iy + 1) * N_INTERP + ix + 1];
        float top = g00 + ax * (g01 - g00);
        float bot = g10 + ax * (g11 - g10);
        float th = top + ay * (bot - top);
        if (th < -PIc * 0.5f) th += PIc;
        th *= osc;

        float rs = fmaxf(rho * amp * a3, 1.0f);
        // 0.45^-a4 * pdur^a4 = exp2(a4*(log2(pdur) - log2(0.45)))
        float ls = lam * ex2_fast(a4 * (__log2f(pdur) - LOG2_045));
        ls = fminf(fmaxf(ls, 0.f), 0.99f);
        bright = a0 * ex2_fast(a1 * __log2f(fmaxf(amp, 1e-5f))) + a2 * freq;

        float t2 = sqrtf(1.0f - ls * ls);
        float sy = __fdividef(rs, TEMP1c * t2);
        float sx = rs * t2 * (1.0f / TEMP1c);
        float s = __sinf(th), c = __cosf(th);
        float cov00 = sx * c * c + sy * s * s;
        float cov01 = (sx - sy) * s * c;
        float cov11 = sx * s * s + sy * c * c;
        float det = cov00 * cov11 - cov01 * cov01;
        float rdet = __fdividef(1.0f, det);
        float inv00 = cov11 * rdet;
        float inv01 = -cov01 * rdet;
        float inv11 = cov00 * rdet;

        c00 = NEG_HALF_LOG2E * inv00;
        c01 = 2.0f * NEG_HALF_LOG2E * inv01;
        c11 = NEG_HALF_LOG2E * inv11;

        cx = (exv / RET_PER_DVA - XRANGE0) / XYSTEP;
        float cy = (float)HH - (eyv / RET_PER_DVA - YRANGE0) / XYSTEP;
        cy2 = 120.0f - cy;   // d1 = cy2 - r
    }
    // inactive electrodes: all zeros -> t=0, ex2(0)=1, bright=0 -> adds 0

    g_tab[b][e * 2 + 0] = make_float4(cx, cy2, 0.f, bright);
    g_tab[b][e * 2 + 1] = make_float4(c00, c01, c11, 2.0f * c11);
}

// ---------------- kernel B: pixel loop + fused combine ----------------
// grid (4, 8, NB*NSPLIT), block 128.  Warp = 32 cols x 4 rows (FD over rows).
// Electrode slice per split: fixed [split*57, ...) (uncompacted, 225 total).
#define CHUNK 57
__global__ __launch_bounds__(128) void mvg_main_kernel(float* __restrict__ out) {
    __shared__ float4 sA[CHUNK];
    __shared__ float4 sB[CHUNK];
    __shared__ int    s_last;

    int bz = blockIdx.z;
    int b = bz >> 2;               // NSPLIT == 4
    int split = bz & 3;
    int e0 = split * CHUNK;
    int len = min(NE - e0, CHUNK);

    int tid = threadIdx.x;
    int lane = tid & 31, w = tid >> 5;

    for (int i = tid; i < len; i += 128) {
        sA[i] = g_tab[b][(e0 + i) * 2 + 0];
        sB[i] = g_tab[b][(e0 + i) * 2 + 1];
    }
    __syncthreads();

    int c  = blockIdx.x * 32 + lane;
    int r0 = blockIdx.y * 16 + w * 4;

    float cf  = (float)c;
    float rf0 = (float)r0;

    float acc0 = 0.f, acc1 = 0.f, acc2 = 0.f, acc3 = 0.f;

    for (int e = 0; e < len; e++) {
        float4 A = sA[e];                       // cx, cy2, -, bright
        float4 B = sB[e];                       // c00, c01, c11, 2*c11
        float d0 = cf - A.x;
        float k1 = B.y * d0;                    // c01*d0
        float k0 = (B.x * d0) * d0;             // c00*d0^2
        float d1 = A.y - rf0;

        float t   = fmaf(fmaf(B.z, d1, k1), d1, k0);
        float dlt = fmaf(B.z, fmaf(-2.0f, d1, 1.0f), -k1);

        acc0 = fmaf(A.w, ex2_fast(t), acc0);
        t += dlt; dlt += B.w;
        acc1 = fmaf(A.w, ex2_fast(t), acc1);
        t += dlt; dlt += B.w;
        acc2 = fmaf(A.w, ex2_fast(t), acc2);
        t += dlt;
        acc3 = fmaf(A.w, ex2_fast(t), acc3);
    }

    float* dst = g_part + (split * NB + b) * NPIX + c;
    if (c < WW) {
        if (r0 + 0 < HH) dst[(r0 + 0) * WW] = acc0;
        if (r0 + 1 < HH) dst[(r0 + 1) * WW] = acc1;
        if (r0 + 2 < HH) dst[(r0 + 2) * WW] = acc2;
        if (r0 + 3 < HH) dst[(r0 + 3) * WW] = acc3;
    }

    // fused combine: last split-block for this (b,tile) sums partials
    __threadfence();
    __syncthreads();
    if (tid == 0) {
        int idx = (b * TILES_X + blockIdx.x) * TILES_Y + blockIdx.y;
        int old = atomicAdd(&g_done[idx], 1);
        s_last = (old == NSPLIT - 1) ? 1 : 0;
        if (s_last) g_done[idx] = 0;      // reset for next graph replay
    }
    __syncthreads();

    if (s_last) {
        int col0 = blockIdx.x * 32;
        int row0 = blockIdx.y * 16;
        for (int k = tid; k < 512; k += 128) {
            int r = row0 + (k >> 5);
            int cc = col0 + (k & 31);
            if (r < HH && cc < WW) {
                int p = r * WW + cc;
                // fixed split order -> deterministic fp sum
                float v = __ldcg(&g_part[(0 * NB + b) * NPIX + p])
                        + __ldcg(&g_part[(1 * NB + b) * NPIX + p])
                        + __ldcg(&g_part[(2 * NB + b) * NPIX + p])
                        + __ldcg(&g_part[(3 * NB + b) * NPIX + p]);
                out[b * NPIX + p] = v;
            }
        }
    }
}

extern "C" void kernel_launch(void* const* d_in, const int* in_sizes, int n_in,
                              void* d_out, int out_size) {
    const float* stim   = (const float*)d_in[0];  // (8,225,3)
    const float* params = (const float*)d_in[1];  // (8,13)
    const float* ex     = (const float*)d_in[2];  // (1,225)
    const float* ey     = (const float*)d_in[3];  // (1,225)
    const float* slopes = (const float*)d_in[4];  // (200,200)
    // d_in[5] = pixelgrid: implied analytically, unused

    dim3 pgrid(8, NB);                             // 64 warps, spread across SMs
    precompute_kernel<<<pgrid, 32>>>(stim, params, ex, ey, slopes);

    dim3 grid(TILES_X, TILES_Y, NB * NSPLIT);      // (4,8,32)
    mvg_main_kernel<<<grid, 128>>>((float*)d_out);
}

// round 10
// speedup vs baseline: 1.0096x; 1.0096x over previous
#include <cuda_runtime.h>
#include <math.h>

// ---------------- constants matching the reference ----------------
#define HH 121
#define WW 121
#define NE 225
#define NB 8
#define NSPLIT 4
#define CHUNK 57                       // ceil(225/4)
#define N_INTERP 200
#define RET_PER_DVA 280.0f
#define XRANGE0 (-15.0f)
#define YRANGE0 (-15.0f)
#define XYSTEP 0.25f
#define XLOWc (-4200.0f)
#define YLOWc (-4200.0f)
#define STEP_Xc (8400.0f/199.0f)
#define STEP_Yc (8400.0f/199.0f)
#define OD_OFF_Xc (15.5f*280.0f)
#define AMP_CUTOFF 0.25f
#define PIc 3.14159265358979323846f
#define TEMP1c (4.0f*PIc)
#define NEG_HALF_LOG2E (-0.7213475204444817f)   // -0.5*log2(e)
#define LOG2_045 (-1.1520030934450498f)         // log2(0.45)
#define CULL_T 25.0f                   // exp2(-25) ~ 3e-8; dropped sum << 1e-3 tol

#define NPIX (HH*WW)
#define TILES_X 4
#define TILES_Y 8

// partial images per electrode-split
__device__ float g_part[NSPLIT * NB * NPIX];
// per-(b, tile) completion counters (statically zero; reset by finisher)
__device__ int   g_done[NB * TILES_X * TILES_Y];

__device__ __forceinline__ float ex2_fast(float x) {
    float r;
    asm("ex2.approx.ftz.f32 %0, %1;" : "=f"(r) : "f"(x));
    return r;
}

// grid (4, 8, NB*NSPLIT), block 128.
// Phase 1: per-electrode params for this block's 57-electrode chunk
//          (4-warp deterministic popc compaction). sA.z holds the cull
//          radius^2 (in the lmin-scaled metric).
// Phase 2: warp tile = 8 cols x 16 rows (lane: lx=lane&7 col, ly=lane>>3
//          selects 4-row strip). Small tile -> tight per-electrode
//          warp-uniform cull; FD over 4 rows for survivors.
// Phase 3: last split-block for this (b,tile) sums partials -> out.
__global__ __launch_bounds__(128) void mvg_main_kernel(
        const float* __restrict__ stim,
        const float* __restrict__ params,
        const float* __restrict__ elec_x,
        const float* __restrict__ elec_y,
        const float* __restrict__ slopes,
        float* __restrict__ out) {
    __shared__ float4 sA[CHUNK];   // cx, cy2, R2cull, bright
    __shared__ float4 sB[CHUNK];   // c00, c01, c11, 2*c11
    __shared__ int    wcnt[4];
    __shared__ int    s_len;
    __shared__ int    s_last;

    int bz = blockIdx.z;
    int b = bz >> 2;               // NSPLIT == 4
    int split = bz & 3;
    int e0 = split * CHUNK;
    int len = min(NE - e0, CHUNK);

    int tid = threadIdx.x;
    int lane = tid & 31, w = tid >> 5;

    // ---------------- phase 1: per-electrode precompute ----------------
    bool act = false;
    float cx = 0.f, cy2 = 0.f, R2c = 0.f, bright = 0.f;
    float c00 = 0.f, c01 = 0.f, c11 = 0.f;

    if (tid < len) {
        int e = e0 + tid;
        const float* P = params + b * 13;
        float rho = P[0], lam = P[1], osc = P[2];
        float a0 = P[3], a1 = P[4], a2 = P[5], a3 = P[6], a4 = P[7];
        float impx = P[8], impy = P[9], rot = P[10], lodx = P[11];
        float cr = __cosf(rot), sr = __sinf(rot);

        float exv = elec_x[e] * cr - elec_y[e] * sr + impx;
        float eyv = elec_x[e] * sr + elec_y[e] * cr + impy;
        float freq = stim[(b * NE + e) * 3 + 0];
        float amp  = stim[(b * NE + e) * 3 + 1];
        float pdur = stim[(b * NE + e) * 3 + 2];

        if (amp > AMP_CUTOFF) {
            act = true;
            float offx = lodx - OD_OFF_Xc;
            float qx = (exv - offx - XLOWc) * (1.0f / STEP_Xc);
            float qy = (eyv - YLOWc) * (1.0f / STEP_Yc);

            float fx = fminf(fmaxf(floorf(qx), 0.f), (float)(N_INTERP - 2));
            float fy = fminf(fmaxf(floorf(qy), 0.f), (float)(N_INTERP - 2));
            int ix = (int)fx, iy = (int)fy;
            float ax = fminf(fmaxf(qx - fx, 0.f), 1.f);
            float ay = fminf(fmaxf(qy - fy, 0.f), 1.f);
            float g00 = slopes[iy * N_INTERP + ix];
            float g01 = slopes[iy * N_INTERP + ix + 1];
            float g10 = slopes[(iy + 1) * N_INTERP + ix];
            float g11 = slopes[(iy + 1) * N_INTERP + ix + 1];
            float top = g00 + ax * (g01 - g00);
            float bot = g10 + ax * (g11 - g10);
            float th = top + ay * (bot - top);
            if (th < -PIc * 0.5f) th += PIc;
            th *= osc;

            float rs = fmaxf(rho * amp * a3, 1.0f);
            // 0.45^-a4 * pdur^a4 = exp2(a4*(log2(pdur) - log2(0.45)))
            float ls = lam * ex2_fast(a4 * (__log2f(pdur) - LOG2_045));
            ls = fminf(fmaxf(ls, 0.f), 0.99f);
            bright = a0 * ex2_fast(a1 * __log2f(fmaxf(amp, 1e-5f))) + a2 * freq;

            float t2 = sqrtf(1.0f - ls * ls);
            float sy = __fdividef(rs, TEMP1c * t2);
            float sx = rs * t2 * (1.0f / TEMP1c);
            float s = __sinf(th), c = __cosf(th);
            float cov00 = sx * c * c + sy * s * s;
            float cov01 = (sx - sy) * s * c;
            float cov11 = sx * s * s + sy * c * c;
            float det = cov00 * cov11 - cov01 * cov01;
            float rdet = __fdividef(1.0f, det);
            float inv00 = cov11 * rdet;
            float inv01 = -cov01 * rdet;
            float inv11 = cov00 * rdet;

            c00 = NEG_HALF_LOG2E * inv00;
            c01 = 2.0f * NEG_HALF_LOG2E * inv01;
            c11 = NEG_HALF_LOG2E * inv11;

            cx = (exv / RET_PER_DVA - XRANGE0) / XYSTEP;
            float cy = (float)HH - (eyv / RET_PER_DVA - YRANGE0) / XYSTEP;
            cy2 = 120.0f - cy;   // d1 = cy2 - r

            // cull radius^2: |t| >= lmin * dist^2, skip when lmin*dist^2 > CULL_T
            // -Q = [[-c00, -c01/2], [-c01/2, -c11]] is pos.def.
            float trn = -(c00 + c11);
            float dQ  = c00 * c11 - 0.25f * c01 * c01;
            float disc = fmaxf(trn * trn - 4.0f * dQ, 0.f);
            float lmin = 0.5f * (trn - sqrtf(disc));
            R2c = __fdividef(CULL_T, fmaxf(lmin, 1e-20f));
        }
    }

    // deterministic popc compaction across 4 warps (ascending e preserved)
    unsigned mask = __ballot_sync(0xffffffffu, act);
    if (lane == 0) wcnt[w] = __popc(mask);
    __syncthreads();
    int off = 0;
#pragma unroll
    for (int i = 0; i < 4; i++) off += (i < w) ? wcnt[i] : 0;
    if (tid == 0) s_len = wcnt[0] + wcnt[1] + wcnt[2] + wcnt[3];
    if (act) {
        int slot = off + __popc(mask & ((1u << lane) - 1u));
        sA[slot] = make_float4(cx, cy2, R2c, bright);
        sB[slot] = make_float4(c00, c01, c11, 2.0f * c11);
    }
    __syncthreads();
    int n = s_len;

    // ---------------- phase 2: pixel loop (8x16 warp tile, cull + FD) ----
    int lx = lane & 7;             // col within warp tile
    int ly = lane >> 3;            // 4-row strip within warp tile
    int c  = blockIdx.x * 32 + w * 8 + lx;
    int r0 = blockIdx.y * 16 + ly * 4;

    float cf  = (float)c;
    float rf0 = (float)r0;

    // warp-uniform tile center: 8 cols x 16 rows
    float wcx = (float)(blockIdx.x * 32 + w * 8) + 3.5f;
    float wcy = (float)(blockIdx.y * 16) + 7.5f;

    float acc0 = 0.f, acc1 = 0.f, acc2 = 0.f, acc3 = 0.f;

    for (int e = 0; e < n; e++) {
        float4 A = sA[e];                       // cx, cy2, R2cull, bright
        // warp-uniform cull: box-to-point distance, dilated tile
        float dx = fmaxf(fabsf(wcx - A.x) - 3.5f, 0.f);
        float dy = fmaxf(fabsf(wcy - A.y) - 7.5f, 0.f);
        if (fmaf(dx, dx, dy * dy) > A.z) continue;

        float4 B = sB[e];                       // c00, c01, c11, 2*c11
        float d0 = cf - A.x;
        float k1 = B.y * d0;                    // c01*d0
        float k0 = (B.x * d0) * d0;             // c00*d0^2
        float d1 = A.y - rf0;

        float t   = fmaf(fmaf(B.z, d1, k1), d1, k0);
        float dlt = fmaf(B.z, fmaf(-2.0f, d1, 1.0f), -k1);

        acc0 = fmaf(A.w, ex2_fast(t), acc0);
        t += dlt; dlt += B.w;
        acc1 = fmaf(A.w, ex2_fast(t), acc1);
        t += dlt; dlt += B.w;
        acc2 = fmaf(A.w, ex2_fast(t), acc2);
        t += dlt;
        acc3 = fmaf(A.w, ex2_fast(t), acc3);
    }

    float* dst = g_part + (split * NB + b) * NPIX + c;
    if (c < WW) {
        if (r0 + 0 < HH) dst[(r0 + 0) * WW] = acc0;
        if (r0 + 1 < HH) dst[(r0 + 1) * WW] = acc1;
        if (r0 + 2 < HH) dst[(r0 + 2) * WW] = acc2;
        if (r0 + 3 < HH) dst[(r0 + 3) * WW] = acc3;
    }

    // ---------------- phase 3: last-block reduction ----------------
    __syncthreads();               // all stores issued; cta-scope ordering
    if (tid == 0) {
        __threadfence();           // cumulative: publishes block's stores gpu-wide
        int idx = (b * TILES_X + blockIdx.x) * TILES_Y + blockIdx.y;
        int old = atomicAdd(&g_done[idx], 1);
        s_last = (old == NSPLIT - 1) ? 1 : 0;
        if (s_last) g_done[idx] = 0;      // reset for next graph replay
    }
    __syncthreads();

    if (s_last) {
        int col0 = blockIdx.x * 32;
        int row0 = blockIdx.y * 16;
        for (int k = tid; k < 512; k += 128) {
            int r = row0 + (k >> 5);
            int cc = col0 + (k & 31);
            if (r < HH && cc < WW) {
                int p = r * WW + cc;
                // fixed split order -> deterministic fp sum
                float v = __ldcg(&g_part[(0 * NB + b) * NPIX + p])
                        + __ldcg(&g_part[(1 * NB + b) * NPIX + p])
                        + __ldcg(&g_part[(2 * NB + b) * NPIX + p])
                        + __ldcg(&g_part[(3 * NB + b) * NPIX + p]);
                out[b * NPIX + p] = v;
            }
        }
    }
}

extern "C" void kernel_launch(void* const* d_in, const int* in_sizes, int n_in,
                              void* d_out, int out_size) {
    const float* stim   = (const float*)d_in[0];  // (8,225,3)
    const float* params = (const float*)d_in[1];  // (8,13)
    const float* ex     = (const float*)d_in[2];  // (1,225)
    const float* ey     = (const float*)d_in[3];  // (1,225)
    const float* slopes = (const float*)d_in[4];  // (200,200)
    // d_in[5] = pixelgrid: implied analytically, unused

    dim3 grid(TILES_X, TILES_Y, NB * NSPLIT);   // (4,8,32)
    mvg_main_kernel<<<grid, 128>>>(stim, params, ex, ey, slopes, (float*)d_out);
}

// round 11
// speedup vs baseline: 1.2518x; 1.2399x over previous
#include <cuda_runtime.h>
#include <math.h>

// ---------------- constants matching the reference ----------------
#define HH 121
#define WW 121
#define NE 225
#define NB 8
#define N_INTERP 200
#define RET_PER_DVA 280.0f
#define XRANGE0 (-15.0f)
#define YRANGE0 (-15.0f)
#define XYSTEP 0.25f
#define XLOWc (-4200.0f)
#define YLOWc (-4200.0f)
#define STEP_Xc (8400.0f/199.0f)
#define STEP_Yc (8400.0f/199.0f)
#define OD_OFF_Xc (15.5f*280.0f)
#define AMP_CUTOFF 0.25f
#define PIc 3.14159265358979323846f
#define TEMP1c (4.0f*PIc)
#define NEG_HALF_LOG2E (-0.7213475204444817f)   // -0.5*log2(e)
#define LOG2_045 (-1.1520030934450498f)         // log2(0.45)

#define NPIX (HH*WW)
#define TILES_X 4
#define TILES_Y 8

__device__ __forceinline__ float ex2_fast(float x) {
    float r;
    asm("ex2.approx.ftz.f32 %0, %1;" : "=f"(r) : "f"(x));
    return r;
}

// ONE kernel. grid (4, 8, NB), block 512 (16 warps).
// Phase 1: threads 0..255 (8 warps) compute per-electrode params for ALL 225
//          electrodes of batch b, deterministic popc compaction into smem.
// Phase 2: warp w -> row-strip (w&3) x electrode-quarter (w>>2).
//          Each warp: 32 cols x 4 rows, FD over rows, ~1/4 of electrodes.
// Phase 3: block-local smem reduction across the 4 quarters in fixed order,
//          plain STG to d_out. No cross-block traffic anywhere.
__global__ __launch_bounds__(512) void mvg_kernel(
        const float* __restrict__ stim,
        const float* __restrict__ params,
        const float* __restrict__ elec_x,
        const float* __restrict__ elec_y,
        const float* __restrict__ slopes,
        float* __restrict__ out) {
    __shared__ float4 sA[NE];          // cx, cy2, -, bright
    __shared__ float4 sB[NE];          // c00, c01, c11, 2*c11
    __shared__ float  spart[4][512];   // [quarter][pixel-in-tile]
    __shared__ int    wcnt[8];
    __shared__ int    s_len;

    int b = blockIdx.z;
    int tid = threadIdx.x;
    int lane = tid & 31, w = tid >> 5;

    // ---------------- phase 1: per-electrode precompute (warps 0-7) ------
    bool act = false;
    float cx = 0.f, cy2 = 0.f, bright = 0.f;
    float c00 = 0.f, c01 = 0.f, c11 = 0.f;

    if (w < 8) {
        if (tid < NE) {
            int e = tid;
            const float* P = params + b * 13;
            float rho = P[0], lam = P[1], osc = P[2];
            float a0 = P[3], a1 = P[4], a2 = P[5], a3 = P[6], a4 = P[7];
            float impx = P[8], impy = P[9], rot = P[10], lodx = P[11];
            float cr = __cosf(rot), sr = __sinf(rot);

            float exv = elec_x[e] * cr - elec_y[e] * sr + impx;
            float eyv = elec_x[e] * sr + elec_y[e] * cr + impy;
            float freq = stim[(b * NE + e) * 3 + 0];
            float amp  = stim[(b * NE + e) * 3 + 1];
            float pdur = stim[(b * NE + e) * 3 + 2];

            if (amp > AMP_CUTOFF) {
                act = true;
                float offx = lodx - OD_OFF_Xc;
                float qx = (exv - offx - XLOWc) * (1.0f / STEP_Xc);
                float qy = (eyv - YLOWc) * (1.0f / STEP_Yc);

                float fx = fminf(fmaxf(floorf(qx), 0.f), (float)(N_INTERP - 2));
                float fy = fminf(fmaxf(floorf(qy), 0.f), (float)(N_INTERP - 2));
                int ix = (int)fx, iy = (int)fy;
                float ax = fminf(fmaxf(qx - fx, 0.f), 1.f);
                float ay = fminf(fmaxf(qy - fy, 0.f), 1.f);
                float g00 = slopes[iy * N_INTERP + ix];
                float g01 = slopes[iy * N_INTERP + ix + 1];
                float g10 = slopes[(iy + 1) * N_INTERP + ix];
                float g11 = slopes[(iy + 1) * N_INTERP + ix + 1];
                float top = g00 + ax * (g01 - g00);
                float bot = g10 + ax * (g11 - g10);
                float th = top + ay * (bot - top);
                if (th < -PIc * 0.5f) th += PIc;
                th *= osc;

                float rs = fmaxf(rho * amp * a3, 1.0f);
                // 0.45^-a4 * pdur^a4 = exp2(a4*(log2(pdur) - log2(0.45)))
                float ls = lam * ex2_fast(a4 * (__log2f(pdur) - LOG2_045));
                ls = fminf(fmaxf(ls, 0.f), 0.99f);
                bright = a0 * ex2_fast(a1 * __log2f(fmaxf(amp, 1e-5f))) + a2 * freq;

                float t2 = sqrtf(1.0f - ls * ls);
                float sy = __fdividef(rs, TEMP1c * t2);
                float sx = rs * t2 * (1.0f / TEMP1c);
                float s = __sinf(th), c = __cosf(th);
                float cov00 = sx * c * c + sy * s * s;
                float cov01 = (sx - sy) * s * c;
                float cov11 = sx * s * s + sy * c * c;
                float det = cov00 * cov11 - cov01 * cov01;
                float rdet = __fdividef(1.0f, det);
                float inv00 = cov11 * rdet;
                float inv01 = -cov01 * rdet;
                float inv11 = cov00 * rdet;

                c00 = NEG_HALF_LOG2E * inv00;
                c01 = 2.0f * NEG_HALF_LOG2E * inv01;
                c11 = NEG_HALF_LOG2E * inv11;

                cx = (exv / RET_PER_DVA - XRANGE0) / XYSTEP;
                float cy = (float)HH - (eyv / RET_PER_DVA - YRANGE0) / XYSTEP;
                cy2 = 120.0f - cy;   // d1 = cy2 - r
            }
        }
        unsigned mask = __ballot_sync(0xffffffffu, act);
        if (lane == 0) wcnt[w] = __popc(mask);
    }
    __syncthreads();

    if (w < 8) {
        int off = 0;
#pragma unroll
        for (int i = 0; i < 8; i++) off += (i < w) ? wcnt[i] : 0;
        if (tid == 0) {
            int tot = 0;
#pragma unroll
            for (int i = 0; i < 8; i++) tot += wcnt[i];
            s_len = tot;
        }
        if (act) {
            unsigned mask = __ballot_sync(__activemask(), true);  // recompute within act-group? no:
            // NOTE: must use the original full-warp ballot; recompute it safely:
        }
    }
    __syncthreads();
    // Redo compaction store with a clean full-warp ballot (all warp lanes active):
    if (w < 8) {
        unsigned mask = __ballot_sync(0xffffffffu, act);
        int off = 0;
#pragma unroll
        for (int i = 0; i < 8; i++) off += (i < w) ? wcnt[i] : 0;
        if (act) {
            int slot = off + __popc(mask & ((1u << lane) - 1u));
            sA[slot] = make_float4(cx, cy2, 0.f, bright);
            sB[slot] = make_float4(c00, c01, c11, 2.0f * c11);
        }
    }
    __syncthreads();
    int n = s_len;

    // ---------------- phase 2: pixel loop --------------------------------
    int q     = w >> 2;            // electrode quarter 0..3
    int strip = w & 3;             // row strip 0..3
    int c  = blockIdx.x * 32 + lane;
    int r0 = blockIdx.y * 16 + strip * 4;

    float cf  = (float)c;
    float rf0 = (float)r0;

    int qlen = (n + 3) >> 2;
    int e0 = q * qlen;
    int e1 = min(n, e0 + qlen);

    float acc0 = 0.f, acc1 = 0.f, acc2 = 0.f, acc3 = 0.f;

    for (int e = e0; e < e1; e++) {
        float4 A = sA[e];                       // cx, cy2, -, bright
        float4 B = sB[e];                       // c00, c01, c11, 2*c11
        float d0 = cf - A.x;
        float k1 = B.y * d0;                    // c01*d0
        float k0 = (B.x * d0) * d0;             // c00*d0^2
        float d1 = A.y - rf0;

        float t   = fmaf(fmaf(B.z, d1, k1), d1, k0);
        float dlt = fmaf(B.z, fmaf(-2.0f, d1, 1.0f), -k1);

        acc0 = fmaf(A.w, ex2_fast(t), acc0);
        t += dlt; dlt += B.w;
        acc1 = fmaf(A.w, ex2_fast(t), acc1);
        t += dlt; dlt += B.w;
        acc2 = fmaf(A.w, ex2_fast(t), acc2);
        t += dlt;
        acc3 = fmaf(A.w, ex2_fast(t), acc3);
    }

    // write partials to smem: pixel index within 32x16 tile
    int p0 = strip * 128 + lane;   // (strip*4 + 0)*32 + lane
    spart[q][p0 +  0] = acc0;
    spart[q][p0 + 32] = acc1;
    spart[q][p0 + 64] = acc2;
    spart[q][p0 + 96] = acc3;
    __syncthreads();

    // ---------------- phase 3: block-local reduction ---------------------
    {
        int p = tid;                           // 0..511
        // fixed quarter order -> deterministic fp sum
        float v = spart[0][p] + spart[1][p] + spart[2][p] + spart[3][p];
        int r  = blockIdx.y * 16 + (p >> 5);
        int cc = blockIdx.x * 32 + (p & 31);
        if (r < HH && cc < WW)
            out[b * NPIX + r * WW + cc] = v;
    }
}

extern "C" void kernel_launch(void* const* d_in, const int* in_sizes, int n_in,
                              void* d_out, int out_size) {
    const float* stim   = (const float*)d_in[0];  // (8,225,3)
    const float* params = (const float*)d_in[1];  // (8,13)
    const float* ex     = (const float*)d_in[2];  // (1,225)
    const float* ey     = (const float*)d_in[3];  // (1,225)
    const float* slopes = (const float*)d_in[4];  // (200,200)
    // d_in[5] = pixelgrid: implied analytically, unused

    dim3 grid(TILES_X, TILES_Y, NB);   // (4,8,8) = 256 blocks x 512 threads
    mvg_kernel<<<grid, 512>>>(stim, params, ex, ey, slopes, (float*)d_out);
}

// round 12
// speedup vs baseline: 1.3208x; 1.0551x over previous
#include <cuda_runtime.h>
#include <math.h>

// ---------------- constants matching the reference ----------------
#define HH 121
#define WW 121
#define NE 225
#define NB 8
#define N_INTERP 200
#define RET_PER_DVA 280.0f
#define XRANGE0 (-15.0f)
#define YRANGE0 (-15.0f)
#define XYSTEP 0.25f
#define XLOWc (-4200.0f)
#define YLOWc (-4200.0f)
#define STEP_Xc (8400.0f/199.0f)
#define STEP_Yc (8400.0f/199.0f)
#define OD_OFF_Xc (15.5f*280.0f)
#define AMP_CUTOFF 0.25f
#define PIc 3.14159265358979323846f
#define TEMP1c (4.0f*PIc)
#define NEG_HALF_LOG2E (-0.7213475204444817f)   // -0.5*log2(e)
#define LOG2_045 (-1.1520030934450498f)         // log2(0.45)
#define CULL_T 22.0f                   // exp2(-22) ~ 2.4e-7 per dropped term

#define NPIX (HH*WW)
#define TILES_X 8                      // 16-col tiles (128 >= 121)
#define TILES_Y 8                      // 16-row tiles

__device__ __forceinline__ float ex2_fast(float x) {
    float r;
    asm("ex2.approx.ftz.f32 %0, %1;" : "=f"(r) : "f"(x));
    return r;
}

// ONE kernel. grid (8, 8, NB) = 512 blocks, block 256 (8 warps).
// Phase 1: all 8 warps compute per-electrode params for the full 225
//          electrodes of batch b; deterministic popc compaction into smem.
//          sA.z = cull radius^2 in the lmin metric.
// Phase 2: every warp covers the SAME 16x16 block tile (lane: lx=lane&15,
//          ly=lane>>4; 8 rows/thread FD), processing the interleaved
//          electrode subset e = w, w+8, w+16, ... with a tight warp-uniform
//          spatial cull (tile dilation only 7.5px).
// Phase 3: block-local smem reduction across the 8 warp-partials in fixed
//          order, plain STG to d_out. No cross-block traffic.
__global__ __launch_bounds__(256) void mvg_kernel(
        const float* __restrict__ stim,
        const float* __restrict__ params,
        const float* __restrict__ elec_x,
        const float* __restrict__ elec_y,
        const float* __restrict__ slopes,
        float* __restrict__ out) {
    __shared__ float4 sA[NE];          // cx, cy2, R2cull, bright
    __shared__ float4 sB[NE];          // c00, c01, c11, 2*c11
    __shared__ float  spart[8][256];   // [warp][pixel-in-tile]
    __shared__ int    wcnt[8];
    __shared__ int    s_len;

    int b = blockIdx.z;
    int tid = threadIdx.x;
    int lane = tid & 31, w = tid >> 5;

    // ---------------- phase 1: per-electrode precompute ------------------
    bool act = false;
    float cx = 0.f, cy2 = 0.f, R2c = 0.f, bright = 0.f;
    float c00 = 0.f, c01 = 0.f, c11 = 0.f;

    if (tid < NE) {
        int e = tid;
        const float* P = params + b * 13;
        float rho = P[0], lam = P[1], osc = P[2];
        float a0 = P[3], a1 = P[4], a2 = P[5], a3 = P[6], a4 = P[7];
        float impx = P[8], impy = P[9], rot = P[10], lodx = P[11];
        float cr = __cosf(rot), sr = __sinf(rot);

        float exv = elec_x[e] * cr - elec_y[e] * sr + impx;
        float eyv = elec_x[e] * sr + elec_y[e] * cr + impy;
        float freq = stim[(b * NE + e) * 3 + 0];
        float amp  = stim[(b * NE + e) * 3 + 1];
        float pdur = stim[(b * NE + e) * 3 + 2];

        if (amp > AMP_CUTOFF) {
            act = true;
            float offx = lodx - OD_OFF_Xc;
            float qx = (exv - offx - XLOWc) * (1.0f / STEP_Xc);
            float qy = (eyv - YLOWc) * (1.0f / STEP_Yc);

            float fx = fminf(fmaxf(floorf(qx), 0.f), (float)(N_INTERP - 2));
            float fy = fminf(fmaxf(floorf(qy), 0.f), (float)(N_INTERP - 2));
            int ix = (int)fx, iy = (int)fy;
            float ax = fminf(fmaxf(qx - fx, 0.f), 1.f);
            float ay = fminf(fmaxf(qy - fy, 0.f), 1.f);
            float g00 = slopes[iy * N_INTERP + ix];
            float g01 = slopes[iy * N_INTERP + ix + 1];
            float g10 = slopes[(iy + 1) * N_INTERP + ix];
            float g11 = slopes[(iy + 1) * N_INTERP + ix + 1];
            float top = g00 + ax * (g01 - g00);
            float bot = g10 + ax * (g11 - g10);
            float th = top + ay * (bot - top);
            if (th < -PIc * 0.5f) th += PIc;
            th *= osc;

            float rs = fmaxf(rho * amp * a3, 1.0f);
            // 0.45^-a4 * pdur^a4 = exp2(a4*(log2(pdur) - log2(0.45)))
            float ls = lam * ex2_fast(a4 * (__log2f(pdur) - LOG2_045));
            ls = fminf(fmaxf(ls, 0.f), 0.99f);
            bright = a0 * ex2_fast(a1 * __log2f(fmaxf(amp, 1e-5f))) + a2 * freq;

            float t2 = sqrtf(1.0f - ls * ls);
            float sy = __fdividef(rs, TEMP1c * t2);
            float sx = rs * t2 * (1.0f / TEMP1c);
            float s = __sinf(th), c = __cosf(th);
            float cov00 = sx * c * c + sy * s * s;
            float cov01 = (sx - sy) * s * c;
            float cov11 = sx * s * s + sy * c * c;
            float det = cov00 * cov11 - cov01 * cov01;
            float rdet = __fdividef(1.0f, det);
            float inv00 = cov11 * rdet;
            float inv01 = -cov01 * rdet;
            float inv11 = cov00 * rdet;

            c00 = NEG_HALF_LOG2E * inv00;
            c01 = 2.0f * NEG_HALF_LOG2E * inv01;
            c11 = NEG_HALF_LOG2E * inv11;

            cx = (exv / RET_PER_DVA - XRANGE0) / XYSTEP;
            float cy = (float)HH - (eyv / RET_PER_DVA - YRANGE0) / XYSTEP;
            cy2 = 120.0f - cy;   // d1 = cy2 - r

            // cull radius^2: |t| >= lmin*dist^2, skip when lmin*dist^2 > CULL_T
            float trn = -(c00 + c11);
            float dQ  = c00 * c11 - 0.25f * c01 * c01;
            float disc = fmaxf(trn * trn - 4.0f * dQ, 0.f);
            float lmin = 0.5f * (trn - sqrtf(disc));
            R2c = __fdividef(CULL_T, fmaxf(lmin, 1e-20f));
        }
    }

    // deterministic popc compaction across 8 warps (ascending e preserved)
    unsigned mask = __ballot_sync(0xffffffffu, act);
    if (lane == 0) wcnt[w] = __popc(mask);
    __syncthreads();
    int off = 0;
#pragma unroll
    for (int i = 0; i < 8; i++) off += (i < w) ? wcnt[i] : 0;
    if (tid == 0) {
        int tot = 0;
#pragma unroll
        for (int i = 0; i < 8; i++) tot += wcnt[i];
        s_len = tot;
    }
    if (act) {
        int slot = off + __popc(mask & ((1u << lane) - 1u));
        sA[slot] = make_float4(cx, cy2, R2c, bright);
        sB[slot] = make_float4(c00, c01, c11, 2.0f * c11);
    }
    __syncthreads();
    int n = s_len;

    // ---------------- phase 2: pixel loop (16x16 tile, cull + 8-row FD) --
    int lx = lane & 15;            // col within tile
    int ly = lane >> 4;            // row-half (8 rows each)
    int c  = blockIdx.x * 16 + lx;
    int r0 = blockIdx.y * 16 + ly * 8;

    float cf  = (float)c;
    float rf0 = (float)r0;

    // warp-uniform tile center (16x16)
    float wcx = (float)(blockIdx.x * 16) + 7.5f;
    float wcy = (float)(blockIdx.y * 16) + 7.5f;

    float acc[8];
#pragma unroll
    for (int i = 0; i < 8; i++) acc[i] = 0.f;

    for (int e = w; e < n; e += 8) {
        float4 A = sA[e];                       // cx, cy2, R2cull, bright
        float dx = fmaxf(fabsf(wcx - A.x) - 7.5f, 0.f);
        float dy = fmaxf(fabsf(wcy - A.y) - 7.5f, 0.f);
        if (fmaf(dx, dx, dy * dy) > A.z) continue;   // warp-uniform cull

        float4 B = sB[e];                       // c00, c01, c11, 2*c11
        float d0 = cf - A.x;
        float k1 = B.y * d0;                    // c01*d0
        float k0 = (B.x * d0) * d0;             // c00*d0^2
        float d1 = A.y - rf0;

        float t   = fmaf(fmaf(B.z, d1, k1), d1, k0);
        float dlt = fmaf(B.z, fmaf(-2.0f, d1, 1.0f), -k1);

#pragma unroll
        for (int i = 0; i < 8; i++) {
            acc[i] = fmaf(A.w, ex2_fast(t), acc[i]);
            t += dlt;
            dlt += B.w;                          // 2*c11
        }
    }

    // partials: pixel index in tile = (ly*8 + i)*16 + lx
    int pbase = ly * 128 + lx;
#pragma unroll
    for (int i = 0; i < 8; i++)
        spart[w][pbase + i * 16] = acc[i];
    __syncthreads();

    // ---------------- phase 3: block-local reduction ---------------------
    {
        // fixed warp order -> deterministic fp sum
        float v = spart[0][tid] + spart[1][tid] + spart[2][tid] + spart[3][tid]
                + spart[4][tid] + spart[5][tid] + spart[6][tid] + spart[7][tid];
        int r  = blockIdx.y * 16 + (tid >> 4);
        int cc = blockIdx.x * 16 + (tid & 15);
        if (r < HH && cc < WW)
            out[b * NPIX + r * WW + cc] = v;
    }
}

extern "C" void kernel_launch(void* const* d_in, const int* in_sizes, int n_in,
                              void* d_out, int out_size) {
    const float* stim   = (const float*)d_in[0];  // (8,225,3)
    const float* params = (const float*)d_in[1];  // (8,13)
    const float* ex     = (const float*)d_in[2];  // (1,225)
    const float* ey     = (const float*)d_in[3];  // (1,225)
    const float* slopes = (const float*)d_in[4];  // (200,200)
    // d_in[5] = pixelgrid: implied analytically, unused

    dim3 grid(TILES_X, TILES_Y, NB);   // (8,8,8) = 512 blocks x 256 threads
    mvg_kernel<<<grid, 256>>>(stim, params, ex, ey, slopes, (float*)d_out);
}

// round 13
// speedup vs baseline: 1.5685x; 1.1875x over previous
#include <cuda_runtime.h>
#include <math.h>

// ---------------- constants matching the reference ----------------
#define HH 121
#define WW 121
#define NE 225
#define NB 8
#define N_INTERP 200
#define RET_PER_DVA 280.0f
#define XRANGE0 (-15.0f)
#define YRANGE0 (-15.0f)
#define XYSTEP 0.25f
#define XLOWc (-4200.0f)
#define YLOWc (-4200.0f)
#define STEP_Xc (8400.0f/199.0f)
#define STEP_Yc (8400.0f/199.0f)
#define OD_OFF_Xc (15.5f*280.0f)
#define AMP_CUTOFF 0.25f
#define PIc 3.14159265358979323846f
#define TEMP1c (4.0f*PIc)
#define NEG_HALF_LOG2E (-0.7213475204444817f)   // -0.5*log2(e)
#define LOG2_045 (-1.1520030934450498f)         // log2(0.45)
#define CULL_T 22.0f                   // exp2(-22) ~ 2.4e-7 per dropped term

#define NPIX (HH*WW)
#define TILES_X 8
#define TILES_Y 8

__device__ __forceinline__ float ex2_fast(float x) {
    float r;
    asm("ex2.approx.ftz.f32 %0, %1;" : "=f"(r) : "f"(x));
    return r;
}

// ONE kernel. grid (8, 8, NB) = 512 blocks, block 256 (8 warps).
// Warp-autonomous: warp w owns electrodes e = w + 8*lane (one per lane).
// Phase 1 (per lane, no cross-warp sync): compute params + cull test for the
//   lane's electrode; one ballot -> survivor mask; survivors stored to a
//   warp-private smem table.
// Phase 2: iterate survivor mask bits only (ffs loop). Warp covers the whole
//   16x16 tile (lx=lane&15, ly=lane>>4), 8-row finite differences.
// Phase 3: block-local reduction of the 8 warp partials in fixed order.
__global__ __launch_bounds__(256) void mvg_kernel(
        const float* __restrict__ stim,
        const float* __restrict__ params,
        const float* __restrict__ elec_x,
        const float* __restrict__ elec_y,
        const float* __restrict__ slopes,
        float* __restrict__ out) {
    __shared__ float4 sTA[8][29];      // warp-private: cx, cy2, -, bright
    __shared__ float4 sTB[8][29];      // warp-private: c00, c01, c11, 2*c11
    __shared__ float  spart[8][256];   // [warp][pixel-in-tile]

    int b = blockIdx.z;
    int tid = threadIdx.x;
    int lane = tid & 31, w = tid >> 5;

    // warp-uniform tile center (16x16 tile)
    float wcx = (float)(blockIdx.x * 16) + 7.5f;
    float wcy = (float)(blockIdx.y * 16) + 7.5f;

    // ---------------- phase 1: per-lane electrode precompute -------------
    int e = w + 8 * lane;              // this lane's electrode
    bool surv = false;

    if (lane < 29 && e < NE) {
        const float* P = params + b * 13;
        float rho = P[0], lam = P[1], osc = P[2];
        float a0 = P[3], a1 = P[4], a2 = P[5], a3 = P[6], a4 = P[7];
        float impx = P[8], impy = P[9], rot = P[10], lodx = P[11];
        float cr = __cosf(rot), sr = __sinf(rot);

        float exv = elec_x[e] * cr - elec_y[e] * sr + impx;
        float eyv = elec_x[e] * sr + elec_y[e] * cr + impy;
        float freq = stim[(b * NE + e) * 3 + 0];
        float amp  = stim[(b * NE + e) * 3 + 1];
        float pdur = stim[(b * NE + e) * 3 + 2];

        if (amp > AMP_CUTOFF) {
            float offx = lodx - OD_OFF_Xc;
            float qx = (exv - offx - XLOWc) * (1.0f / STEP_Xc);
            float qy = (eyv - YLOWc) * (1.0f / STEP_Yc);

            float fx = fminf(fmaxf(floorf(qx), 0.f), (float)(N_INTERP - 2));
            float fy = fminf(fmaxf(floorf(qy), 0.f), (float)(N_INTERP - 2));
            int ix = (int)fx, iy = (int)fy;
            float ax = fminf(fmaxf(qx - fx, 0.f), 1.f);
            float ay = fminf(fmaxf(qy - fy, 0.f), 1.f);
            float g00 = slopes[iy * N_INTERP + ix];
            float g01 = slopes[iy * N_INTERP + ix + 1];
            float g10 = slopes[(iy + 1) * N_INTERP + ix];
            float g11 = slopes[(iy + 1) * N_INTERP + ix + 1];
            float top = g00 + ax * (g01 - g00);
            float bot = g10 + ax * (g11 - g10);
            float th = top + ay * (bot - top);
            if (th < -PIc * 0.5f) th += PIc;
            th *= osc;

            float rs = fmaxf(rho * amp * a3, 1.0f);
            // 0.45^-a4 * pdur^a4 = exp2(a4*(log2(pdur) - log2(0.45)))
            float ls = lam * ex2_fast(a4 * (__log2f(pdur) - LOG2_045));
            ls = fminf(fmaxf(ls, 0.f), 0.99f);
            float bright = a0 * ex2_fast(a1 * __log2f(fmaxf(amp, 1e-5f))) + a2 * freq;

            float t2 = sqrtf(1.0f - ls * ls);
            float sy = __fdividef(rs, TEMP1c * t2);
            float sx = rs * t2 * (1.0f / TEMP1c);
            float s = __sinf(th), c = __cosf(th);
            float cov00 = sx * c * c + sy * s * s;
            float cov01 = (sx - sy) * s * c;
            float cov11 = sx * s * s + sy * c * c;
            float det = cov00 * cov11 - cov01 * cov01;
            float rdet = __fdividef(1.0f, det);
            float inv00 = cov11 * rdet;
            float inv01 = -cov01 * rdet;
            float inv11 = cov00 * rdet;

            float c00 = NEG_HALF_LOG2E * inv00;
            float c01 = 2.0f * NEG_HALF_LOG2E * inv01;
            float c11 = NEG_HALF_LOG2E * inv11;

            float cx = (exv / RET_PER_DVA - XRANGE0) / XYSTEP;
            float cy = (float)HH - (eyv / RET_PER_DVA - YRANGE0) / XYSTEP;
            float cy2 = 120.0f - cy;   // d1 = cy2 - r

            // cull: |t| >= lmin * dist^2; keep iff lmin*dist^2 <= CULL_T
            float trn = -(c00 + c11);
            float dQ  = c00 * c11 - 0.25f * c01 * c01;
            float disc = fmaxf(trn * trn - 4.0f * dQ, 0.f);
            float lmin = 0.5f * (trn - sqrtf(disc));
            float R2c = __fdividef(CULL_T, fmaxf(lmin, 1e-20f));

            float dx = fmaxf(fabsf(wcx - cx) - 7.5f, 0.f);
            float dy = fmaxf(fabsf(wcy - cy2) - 7.5f, 0.f);
            surv = (fmaf(dx, dx, dy * dy) <= R2c);

            if (surv) {
                sTA[w][lane] = make_float4(cx, cy2, 0.f, bright);
                sTB[w][lane] = make_float4(c00, c01, c11, 2.0f * c11);
            }
        }
    }

    unsigned mask = __ballot_sync(0xffffffffu, surv);
    __syncwarp();

    // ---------------- phase 2: survivor loop (16x16 tile, 8-row FD) ------
    int lx = lane & 15;
    int ly = lane >> 4;
    int c  = blockIdx.x * 16 + lx;
    int r0 = blockIdx.y * 16 + ly * 8;

    float cf  = (float)c;
    float rf0 = (float)r0;

    float acc[8];
#pragma unroll
    for (int i = 0; i < 8; i++) acc[i] = 0.f;

    unsigned m = mask;
    while (m) {
        int i = __ffs(m) - 1;          // ascending lane -> ascending e
        m &= m - 1;
        float4 A = sTA[w][i];          // cx, cy2, -, bright
        float4 B = sTB[w][i];          // c00, c01, c11, 2*c11

        float d0 = cf - A.x;
        float k1 = B.y * d0;           // c01*d0
        float k0 = (B.x * d0) * d0;    // c00*d0^2
        float d1 = A.y - rf0;

        float t   = fmaf(fmaf(B.z, d1, k1), d1, k0);
        float dlt = fmaf(B.z, fmaf(-2.0f, d1, 1.0f), -k1);

#pragma unroll
        for (int i2 = 0; i2 < 8; i2++) {
            acc[i2] = fmaf(A.w, ex2_fast(t), acc[i2]);
            t += dlt;
            dlt += B.w;                // 2*c11
        }
    }

    // partials: pixel index in tile = (ly*8 + i)*16 + lx
    int pbase = ly * 128 + lx;
#pragma unroll
    for (int i = 0; i < 8; i++)
        spart[w][pbase + i * 16] = acc[i];
    __syncthreads();

    // ---------------- phase 3: block-local reduction ---------------------
    {
        // fixed warp order -> deterministic fp sum
        float v = spart[0][tid] + spart[1][tid] + spart[2][tid] + spart[3][tid]
                + spart[4][tid] + spart[5][tid] + spart[6][tid] + spart[7][tid];
        int r  = blockIdx.y * 16 + (tid >> 4);
        int cc = blockIdx.x * 16 + (tid & 15);
        if (r < HH && cc < WW)
            out[b * NPIX + r * WW + cc] = v;
    }
}

extern "C" void kernel_launch(void* const* d_in, const int* in_sizes, int n_in,
                              void* d_out, int out_size) {
    const float* stim   = (const float*)d_in[0];  // (8,225,3)
    const float* params = (const float*)d_in[1];  // (8,13)
    const float* ex     = (const float*)d_in[2];  // (1,225)
    const float* ey     = (const float*)d_in[3];  // (1,225)
    const float* slopes = (const float*)d_in[4];  // (200,200)
    // d_in[5] = pixelgrid: implied analytically, unused

    dim3 grid(TILES_X, TILES_Y, NB);   // (8,8,8) = 512 blocks x 256 threads
    mvg_kernel<<<grid, 256>>>(stim, params, ex, ey, slopes, (float*)d_out);
}